// round 11
// baseline (speedup 1.0000x reference)
#include <cuda_runtime.h>
#include <cuda_fp16.h>
#include <cuda_bf16.h>
#include <math.h>
#include <stdint.h>

#define N_SRC 100000
#define N_DST 50000
#define D_IN  128
#define D_OUT 64
#define BUCKET 128

#define TILES_Y 1563           // ceil(100000/64)
#define TILES_Z 782            // ceil(50000/64)
#define ASTR 136

// ---------------- scratch (device globals; no allocations allowed) ---------
__device__ __half g_yh[(size_t)N_SRC * D_OUT];     // fp16(x @ W_l)   12.8 MB
__device__ float  g_z[(size_t)N_DST * D_OUT];      // x[:N_DST]@W_r   12.8 MB
__device__ int    g_cnt[N_DST];
__device__ int    g_src[(size_t)N_DST * BUCKET];   // bucketed CSR    25.6 MB
// Pre-swizzled B fragments (exact ldmatrix register images), per type:
// index [(k*4+p)*32 + lane] -> uint4 = (u0,u1,u2,u3)
__device__ uint4 g_bf1[2][1024];                   // W hi part, 32 KB
__device__ uint4 g_bf2[2][1024];                   // W lo part, 32 KB

__device__ __forceinline__ uint32_t smem_u32(const void* p) {
    uint32_t a;
    asm("{ .reg .u64 t; cvta.to.shared.u64 t, %1; cvt.u32.u64 %0, t; }"
        : "=r"(a) : "l"(p));
    return a;
}

// ---------------------------------------------------------------------------
// prep: per-type (blockIdx.x: 0=W_l, 1=W_r) build bf16 hi/lo W^T tiles in
// smem, then warp 0 runs the gemm's exact b-ldmatrix pattern and stores the
// fragment registers to global. Does NOT touch g_cnt/g_src (side stream owns).
__global__ __launch_bounds__(256) void prep_kernel(const float* __restrict__ Wl,
                                                   const float* __restrict__ Wr) {
    extern __shared__ __align__(16) char psm[];
    __nv_bfloat16* B1 = (__nv_bfloat16*)psm;          // 64 x 136
    __nv_bfloat16* B2 = B1 + 64 * ASTR;
    int type = blockIdx.x;
    const float* W = type ? Wr : Wl;
    int tid = threadIdx.x;

    for (int i = tid; i < 64 * 128; i += 256) {
        int n = i >> 7, k = i & 127;
        float v = W[k * 64 + n];                       // W^T[n][k]
        __nv_bfloat16 h = __float2bfloat16(v);
        B1[n * ASTR + k] = h;
        B2[n * ASTR + k] = __float2bfloat16(v - __bfloat162float(h));
    }
    __syncthreads();

    if (tid < 32) {
        int lane = tid;
        uint32_t b1b = smem_u32(B1), b2b = smem_u32(B2);
        uint32_t boff = (((((lane >> 4) << 3) + (lane & 7)) * ASTR +
                         (((lane >> 3) & 1) << 3)) << 1);
        #pragma unroll
        for (int k = 0; k < 8; k++) {
            #pragma unroll
            for (int p = 0; p < 4; p++) {
                uint32_t po = ((p * ASTR) << 5) + (k << 5);
                uint32_t u0, u1, u2, u3, w0, w1, w2, w3;
                asm volatile("ldmatrix.sync.aligned.m8n8.x4.shared.b16 {%0,%1,%2,%3}, [%4];"
                             : "=r"(u0), "=r"(u1), "=r"(u2), "=r"(u3)
                             : "r"(b1b + boff + po));
                asm volatile("ldmatrix.sync.aligned.m8n8.x4.shared.b16 {%0,%1,%2,%3}, [%4];"
                             : "=r"(w0), "=r"(w1), "=r"(w2), "=r"(w3)
                             : "r"(b2b + boff + po));
                int fi = ((k << 2) + p) * 32 + lane;
                g_bf1[type][fi] = make_uint4(u0, u1, u2, u3);
                g_bf2[type][fi] = make_uint4(w0, w1, w2, w3);
            }
        }
    }
}
#define SM_PREP (2 * 64 * ASTR * 2)

// ---------------------------------------------------------------------------
__global__ void zero_cnt_kernel() {
    int i = blockIdx.x * blockDim.x + threadIdx.x;
    if (i < N_DST) g_cnt[i] = 0;
}

__global__ void fill_kernel(const void* __restrict__ eiv, int n_edges) {
    const unsigned long long* q = (const unsigned long long*)eiv;
    bool is64 = (((q[0] | q[1] | q[2] | q[3]) >> 32) == 0ULL);

    int stride = gridDim.x * blockDim.x;
    for (int e = blockIdx.x * blockDim.x + threadIdx.x; e < n_edges; e += stride) {
        int s, d;
        if (is64) {
            const long long* ei = (const long long*)eiv;
            s = (int)ei[e];
            d = (int)ei[n_edges + e];
        } else {
            const int* ei = (const int*)eiv;
            s = ei[e];
            d = ei[n_edges + e];
        }
        int slot = atomicAdd(&g_cnt[d], 1);
        if (slot < BUCKET)
            g_src[(size_t)d * BUCKET + slot] = s;
    }
}

// ---------------------------------------------------------------------------
// HMMA GEMM: 64x64 tile per CTA, 4 warps, 4 CTAs/SM (A-only smem, capped regs).
// D = A1@W1 + A1@W2 + A2@W1; B fragments come pre-swizzled from global.
__global__ __launch_bounds__(128, 4) void gemm_mma_kernel(const float* __restrict__ x) {
    extern __shared__ __align__(16) char smem_raw[];
    __nv_bfloat16* A1 = (__nv_bfloat16*)smem_raw;            // 64 x 136
    __nv_bfloat16* A2 = A1 + 64 * ASTR;

    int tid = threadIdx.x, warp = tid >> 5, lane = tid & 31;

    int b = blockIdx.x;
    bool is_y;
    int row0, M;
    if (b < TILES_Y) { row0 = b << 6;             M = N_SRC; is_y = true;  }
    else             { row0 = (b - TILES_Y) << 6; M = N_DST; is_y = false; }
    const uint4* bf1 = g_bf1[is_y ? 0 : 1];
    const uint4* bf2 = g_bf2[is_y ? 0 : 1];

    // Load x tile (64x128 fp32), split to bf16 hi/lo
    #pragma unroll
    for (int i = tid; i < 64 * 32; i += 128) {
        int row = i >> 5, c4 = (i & 31) << 2;
        float4 v = make_float4(0.f, 0.f, 0.f, 0.f);
        if (row0 + row < M)
            v = *(const float4*)(x + (size_t)(row0 + row) * D_IN + c4);
        __nv_bfloat16 h0 = __float2bfloat16(v.x), h1 = __float2bfloat16(v.y);
        __nv_bfloat16 h2 = __float2bfloat16(v.z), h3 = __float2bfloat16(v.w);
        __nv_bfloat16 r0 = __float2bfloat16(v.x - __bfloat162float(h0));
        __nv_bfloat16 r1 = __float2bfloat16(v.y - __bfloat162float(h1));
        __nv_bfloat16 r2 = __float2bfloat16(v.z - __bfloat162float(h2));
        __nv_bfloat16 r3 = __float2bfloat16(v.w - __bfloat162float(h3));
        int idx = row * ASTR + c4;
        uint2 hi, lo;
        hi.x = (uint32_t)__bfloat16_as_ushort(h0) | ((uint32_t)__bfloat16_as_ushort(h1) << 16);
        hi.y = (uint32_t)__bfloat16_as_ushort(h2) | ((uint32_t)__bfloat16_as_ushort(h3) << 16);
        lo.x = (uint32_t)__bfloat16_as_ushort(r0) | ((uint32_t)__bfloat16_as_ushort(r1) << 16);
        lo.y = (uint32_t)__bfloat16_as_ushort(r2) | ((uint32_t)__bfloat16_as_ushort(r3) << 16);
        *(uint2*)(A1 + idx) = hi;
        *(uint2*)(A2 + idx) = lo;
    }
    __syncthreads();

    int m0 = warp << 4;
    float c[8][4];
    #pragma unroll
    for (int n = 0; n < 8; n++)
        #pragma unroll
        for (int j = 0; j < 4; j++) c[n][j] = 0.f;

    uint32_t a1b = smem_u32(A1), a2b = smem_u32(A2);
    uint32_t aoff = (((m0 + (lane & 15)) * ASTR + ((lane >> 4) << 3)) << 1);

    #pragma unroll 2
    for (int k = 0; k < 8; k++) {
        uint32_t ka = (k << 5);
        uint32_t x0, x1, x2, x3, y0, y1, y2, y3;
        asm volatile("ldmatrix.sync.aligned.m8n8.x4.shared.b16 {%0,%1,%2,%3}, [%4];"
                     : "=r"(x0), "=r"(x1), "=r"(x2), "=r"(x3)
                     : "r"(a1b + aoff + ka));
        asm volatile("ldmatrix.sync.aligned.m8n8.x4.shared.b16 {%0,%1,%2,%3}, [%4];"
                     : "=r"(y0), "=r"(y1), "=r"(y2), "=r"(y3)
                     : "r"(a2b + aoff + ka));
        #pragma unroll
        for (int p = 0; p < 4; p++) {
            int fi = ((k << 2) + p) * 32 + lane;
            uint4 U = bf1[fi];
            uint4 W4 = bf2[fi];
            int n = p << 1;
            #define MMA(CN, AA0, AA1, AA2, AA3, B0, B1v)                        \
                asm volatile(                                                   \
                    "mma.sync.aligned.m16n8k16.row.col.f32.bf16.bf16.f32 "      \
                    "{%0,%1,%2,%3}, {%4,%5,%6,%7}, {%8,%9}, {%0,%1,%2,%3};"     \
                    : "+f"(c[CN][0]), "+f"(c[CN][1]), "+f"(c[CN][2]), "+f"(c[CN][3]) \
                    : "r"(AA0), "r"(AA1), "r"(AA2), "r"(AA3), "r"(B0), "r"(B1v))
            MMA(n,     x0, x1, x2, x3, U.x, U.y);    // A1*B1
            MMA(n + 1, x0, x1, x2, x3, U.z, U.w);
            MMA(n,     x0, x1, x2, x3, W4.x, W4.y);  // A1*B2
            MMA(n + 1, x0, x1, x2, x3, W4.z, W4.w);
            MMA(n,     y0, y1, y2, y3, U.x, U.y);    // A2*B1
            MMA(n + 1, y0, y1, y2, y3, U.z, U.w);
            #undef MMA
        }
    }

    // Epilogue: c fragment (row gr=lane/4 [+8], cols n*8 + 2*(lane%4) +{0,1})
    int gr = lane >> 2, gc = (lane & 3) << 1;
    int r0 = row0 + m0 + gr;
    int r1 = r0 + 8;
    if (is_y) {
        #pragma unroll
        for (int n = 0; n < 8; n++) {
            int col = (n << 3) + gc;
            if (r0 < M)
                *(__half2*)(g_yh + (size_t)r0 * D_OUT + col) =
                    __floats2half2_rn(c[n][0], c[n][1]);
            if (r1 < M)
                *(__half2*)(g_yh + (size_t)r1 * D_OUT + col) =
                    __floats2half2_rn(c[n][2], c[n][3]);
        }
    } else {
        #pragma unroll
        for (int n = 0; n < 8; n++) {
            int col = (n << 3) + gc;
            if (r0 < M)
                *(float2*)(g_z + (size_t)r0 * D_OUT + col) = make_float2(c[n][0], c[n][1]);
            if (r1 < M)
                *(float2*)(g_z + (size_t)r1 * D_OUT + col) = make_float2(c[n][2], c[n][3]);
        }
    }
}
#define SM_GEMM (2 * 64 * ASTR * 2)

// ---------------------------------------------------------------------------
// Gather + finalize: one warp per dst row; lane owns cols {2l, 2l+1} (half2).
// Full chunks of 8 edges run UNCONDITIONALLY (MLP=8, no per-load predication);
// small tail loop handles the remainder. Depth-3 __hadd2 tree + packed f32x2.
__global__ __launch_bounds__(256) void gather_finalize_kernel(
        float* __restrict__ out, const float* __restrict__ b_l) {
    int warp = (blockIdx.x * blockDim.x + threadIdx.x) >> 5;
    int lane = threadIdx.x & 31;
    if (warp >= N_DST) return;

    int cnt = g_cnt[warp];
    int n = cnt < BUCKET ? cnt : BUCKET;
    const int* bucket = g_src + (size_t)warp * BUCKET;
    const __half2* yh = (const __half2*)g_yh + lane;   // row r -> yh[r*32]

    unsigned long long acc = 0ULL;                     // packed float2
    int nf = n & ~7;
    if (nf > 0) {
        int4 p0 = *(const int4*)bucket;
        int4 p1 = *(const int4*)(bucket + 4);
        for (int g = 0; g < nf; g += 8) {
            int4 c0 = p0, c1 = p1;
            if (g + 8 < nf) {
                p0 = *(const int4*)(bucket + g + 8);
                p1 = *(const int4*)(bucket + g + 12);
            }
            __half2 h0 = yh[(size_t)c0.x << 5];
            __half2 h1 = yh[(size_t)c0.y << 5];
            __half2 h2 = yh[(size_t)c0.z << 5];
            __half2 h3 = yh[(size_t)c0.w << 5];
            __half2 h4 = yh[(size_t)c1.x << 5];
            __half2 h5 = yh[(size_t)c1.y << 5];
            __half2 h6 = yh[(size_t)c1.z << 5];
            __half2 h7 = yh[(size_t)c1.w << 5];
            __half2 t = __hadd2(__hadd2(__hadd2(h0, h1), __hadd2(h2, h3)),
                                __hadd2(__hadd2(h4, h5), __hadd2(h6, h7)));
            float2 f = __half22float2(t);
            unsigned long long fp;
            asm("mov.b64 %0, {%1, %2};" : "=l"(fp) : "f"(f.x), "f"(f.y));
            asm("add.rn.f32x2 %0, %0, %1;" : "+l"(acc) : "l"(fp));
        }
    }
    if (nf < n) {
        float tx = 0.f, ty = 0.f;
        for (int g = nf; g < n; g++) {
            float2 f = __half22float2(yh[(size_t)bucket[g] << 5]);
            tx += f.x;
            ty += f.y;
        }
        unsigned long long fp;
        asm("mov.b64 %0, {%1, %2};" : "=l"(fp) : "f"(tx), "f"(ty));
        asm("add.rn.f32x2 %0, %0, %1;" : "+l"(acc) : "l"(fp));
    }

    float a0, a1;
    asm("mov.b64 {%0, %1}, %2;" : "=f"(a0), "=f"(a1) : "l"(acc));

    float inv = 1.0f / fmaxf((float)cnt, 1.0f);
    float2 zz = *(const float2*)(g_z + (size_t)warp * D_OUT + (lane << 1));
    float2 bb = *(const float2*)(b_l + (lane << 1));
    float v0 = a0 * inv + bb.x + zz.x;
    float v1 = a1 * inv + bb.y + zz.y;

    float m = fmaxf(v0, v1);
    #pragma unroll
    for (int o = 16; o; o >>= 1) m = fmaxf(m, __shfl_xor_sync(0xffffffffu, m, o));

    float s = __expf(v0 - m) + __expf(v1 - m);
    #pragma unroll
    for (int o = 16; o; o >>= 1) s += __shfl_xor_sync(0xffffffffu, s, o);

    float lz = m + __logf(s);
    *(float2*)(out + (size_t)warp * D_OUT + (lane << 1)) =
        make_float2(v0 - lz, v1 - lz);
}

// ---------------------------------------------------------------------------
extern "C" void kernel_launch(void* const* d_in, const int* in_sizes, int n_in,
                              void* d_out, int out_size) {
    const float* x  = (const float*)d_in[0];
    const float* Wl = (const float*)d_in[1];
    const float* bl = (const float*)d_in[2];
    const float* Wr = (const float*)d_in[3];
    const void*  ei = d_in[4];
    int n_edges = in_sizes[4] / 2;
    float* out = (float*)d_out;

    // One-time resources for the forked-stream graph topology (no device mem).
    static cudaStream_t side = nullptr;
    static cudaEvent_t ev_fork = nullptr, ev_join = nullptr;
    if (side == nullptr) {
        cudaStreamCreateWithFlags(&side, cudaStreamNonBlocking);
        cudaEventCreateWithFlags(&ev_fork, cudaEventDisableTiming);
        cudaEventCreateWithFlags(&ev_join, cudaEventDisableTiming);
        cudaFuncSetAttribute(prep_kernel,
                             cudaFuncAttributeMaxDynamicSharedMemorySize, SM_PREP);
        cudaFuncSetAttribute(gemm_mma_kernel,
                             cudaFuncAttributeMaxDynamicSharedMemorySize, SM_GEMM);
    }

    // Fork: CSR build (zero + fill) runs alongside prep + GEMM.
    // The side stream has EXCLUSIVE ownership of g_cnt/g_src until ev_join.
    cudaEventRecord(ev_fork, 0);
    cudaStreamWaitEvent(side, ev_fork, 0);
    zero_cnt_kernel<<<(N_DST + 255) / 256, 256, 0, side>>>();
    fill_kernel<<<2048, 256, 0, side>>>(ei, n_edges);
    cudaEventRecord(ev_join, side);

    // Main stream: W split + fragment prepack, then tensor-core projections.
    prep_kernel<<<2, 256, SM_PREP>>>(Wl, Wr);
    gemm_mma_kernel<<<TILES_Y + TILES_Z, 128, SM_GEMM>>>(x);

    // Join, then gather + finalize.
    cudaStreamWaitEvent(0, ev_join, 0);
    gather_finalize_kernel<<<(N_DST * 32 + 255) / 256, 256>>>(out, bl);
}